// round 13
// baseline (speedup 1.0000x reference)
#include <cuda_runtime.h>
#include <cuda_fp16.h>
#include <cstdint>

// ---------------------------------------------------------------------------
// SAGE_37203006718147: 3-layer GraphSAGE on sm_103a.
// L0 aggregation: edges grouped by dst (hist -> 50k scan -> scatter of src
// ids), then warp-per-dst gather of fp16 x-mirror with fp32 register
// accumulation -> agg0 rows written ONCE (no feature REDs, L2 relief).
// Per layer (fork-join on two captured streams):
//   [default] aggregation   ||  [s2] x16 convert + self-GEMMs
//   join -> [default] neigh-GEMM: RED-accumulate invd[m]*(agg@Wn) into out
// relu (layer-1 output) deferred to the consumers of h2 (exact).
// GEMM: mma.sync fp16 1-term, fp32 accumulate, BK=64, CTA tile 128x128.
// tcgen05 unavailable: harness compiles at virtual arch compute_103 (no 'a').
// ---------------------------------------------------------------------------

#define N0C 200000
#define N1C 50000
#define N2C 12000
#define N3C 3000
#define DF  256
#define E0MAX 500000

// ---- L0 grouping scratch ----
__device__ int    g_cnt [N1C];
__device__ int    g_off [N1C + 1];
__device__ int    g_cur [N1C];
__device__ float  g_degf[N1C];
__device__ int    g_ssrc[E0MAX];
__device__ float  g_agg0[N1C * DF];
__device__ __half g_x16 [N0C * DF];
// ---- L1/L2 scratch (one memset on s2): agg1|deg1|agg2|deg2 ----
#define AGG1_OFF 0
#define DEG1_OFF (N2C * DF)
#define AGG2_OFF (DEG1_OFF + N2C)
#define DEG2_OFF (AGG2_OFF + N3C * DF)
#define SCR_TOT  (DEG2_OFF + N3C)
__device__ float  g_scr[SCR_TOT];
__device__ float  g_h1 [N1C * DF];
__device__ float  g_h2 [N2C * DF];
// transposed fp16 weights: [N][K=512] = [Ws ; Wn], K-major
__device__ __half g_wt0[256 * 512];
__device__ __half g_wt1[256 * 512];
__device__ __half g_wt2[64 * 512];

// ---------------------------------------------------------------------------
// helpers
// ---------------------------------------------------------------------------
__device__ __forceinline__ uint32_t smem_u32(const void* p) {
    uint32_t a;
    asm("{ .reg .u64 t; cvta.to.shared.u64 t, %1; cvt.u32.u64 %0, t; }"
        : "=r"(a) : "l"(p));
    return a;
}

__device__ __forceinline__ void ldsm4(uint32_t* r, uint32_t addr) {
    asm volatile("ldmatrix.sync.aligned.m8n8.x4.shared.b16 {%0,%1,%2,%3}, [%4];"
                 : "=r"(r[0]), "=r"(r[1]), "=r"(r[2]), "=r"(r[3]) : "r"(addr));
}

__device__ __forceinline__ void mma16816(float* c, const uint32_t* a,
                                         const uint32_t* b) {
    asm volatile(
        "mma.sync.aligned.m16n8k16.row.col.f32.f16.f16.f32 "
        "{%0,%1,%2,%3}, {%4,%5,%6,%7}, {%8,%9}, {%0,%1,%2,%3};"
        : "+f"(c[0]), "+f"(c[1]), "+f"(c[2]), "+f"(c[3])
        : "r"(a[0]), "r"(a[1]), "r"(a[2]), "r"(a[3]), "r"(b[0]), "r"(b[1]));
}

// convert 8 fp32 -> 8 packed fp16 (uint4)
__device__ __forceinline__ uint4 cvt8(float4 a, float4 b) {
    float f[8] = {a.x, a.y, a.z, a.w, b.x, b.y, b.z, b.w};
    uint32_t H[8];
#pragma unroll
    for (int i = 0; i < 8; i++)
        H[i] = (uint32_t)__half_as_ushort(__float2half_rn(f[i]));
    uint4 r;
    r.x = H[0] | (H[1] << 16); r.y = H[2] | (H[3] << 16);
    r.z = H[4] | (H[5] << 16); r.w = H[6] | (H[7] << 16);
    return r;
}

// ---------------------------------------------------------------------------
// fp32 -> fp16 bulk convert (8 elems/thread)
// ---------------------------------------------------------------------------
__global__ void convert_fp16(const float* __restrict__ in,
                             __half* __restrict__ out, int n8)
{
    int i = blockIdx.x * blockDim.x + threadIdx.x;
    if (i >= n8) return;
    float4 a = __ldg((const float4*)in + 2 * i);
    float4 b = __ldg((const float4*)in + 2 * i + 1);
    ((uint4*)out)[i] = cvt8(a, b);
}

// ---------------------------------------------------------------------------
// L0 dst-grouping: count -> scan(50k, single block) -> scatter src ids
// ---------------------------------------------------------------------------
__global__ void deg_hist(const int* __restrict__ dst, int E,
                         int* __restrict__ cnt)
{
    int i = blockIdx.x * blockDim.x + threadIdx.x;
    if (i < E) atomicAdd(&cnt[__ldg(dst + i)], 1);
}

__global__ void deg_scan(const int* __restrict__ cnt,
                         int* __restrict__ off, int* __restrict__ cur,
                         float* __restrict__ degf, int E)
{
    __shared__ int tot[1024];
    const int C = (N1C + 1023) / 1024;   // 49
    int t = threadIdx.x;
    int base = t * C;
    int sum = 0;
#pragma unroll 1
    for (int i = 0; i < C; i++) {
        int idx = base + i;
        if (idx < N1C) sum += __ldg(cnt + idx);
    }
    tot[t] = sum;
    __syncthreads();
#pragma unroll
    for (int o = 1; o < 1024; o <<= 1) {
        int u = (t >= o) ? tot[t - o] : 0;
        __syncthreads();
        tot[t] += u;
        __syncthreads();
    }
    int run = tot[t] - sum;   // exclusive prefix for this thread's chunk
#pragma unroll 1
    for (int i = 0; i < C; i++) {
        int idx = base + i;
        if (idx < N1C) {
            int v = __ldg(cnt + idx);
            off[idx]  = run;
            cur[idx]  = run;
            degf[idx] = (float)v;
            run += v;
        }
    }
    if (t == 1023) off[N1C] = E;
}

__global__ void edge_scatter0(const int* __restrict__ src,
                              const int* __restrict__ dst, int E,
                              int* __restrict__ cur, int* __restrict__ ssrc)
{
    int i = blockIdx.x * blockDim.x + threadIdx.x;
    if (i >= E) return;
    int pos = atomicAdd(&cur[__ldg(dst + i)], 1);
    ssrc[pos] = __ldg(src + i);
}

// ---------------------------------------------------------------------------
// L0 aggregate: one warp per dst node. Gather fp16 rows (1 uint4/lane/row),
// accumulate fp32 in registers, write the agg row once. No feature atomics.
// ---------------------------------------------------------------------------
__global__ void sage_agg0_grouped(const __half* __restrict__ x16,
                                  const int* __restrict__ ssrc,
                                  const int* __restrict__ off,
                                  float* __restrict__ agg)
{
    int w = (int)(blockIdx.x * (blockDim.x >> 5) + (threadIdx.x >> 5));
    if (w >= N1C) return;
    int lane = threadIdx.x & 31;
    int s = __ldg(off + w), e = __ldg(off + w + 1);

    float acc[8] = {};
#pragma unroll 1
    while (s < e) {
        int nb = e - s;
        if (nb > 4) nb = 4;
        uint4 v[4];
#pragma unroll
        for (int b = 0; b < 4; b++) {
            if (b < nb) {
                int row = __ldg(ssrc + s + b);
                v[b] = __ldg((const uint4*)(x16 + (size_t)row * DF) + lane);
            }
        }
#pragma unroll
        for (int b = 0; b < 4; b++) {
            if (b < nb) {
                float2 f0 = __half22float2(*(__half2*)&v[b].x);
                float2 f1 = __half22float2(*(__half2*)&v[b].y);
                float2 f2 = __half22float2(*(__half2*)&v[b].z);
                float2 f3 = __half22float2(*(__half2*)&v[b].w);
                acc[0] += f0.x; acc[1] += f0.y;
                acc[2] += f1.x; acc[3] += f1.y;
                acc[4] += f2.x; acc[5] += f2.y;
                acc[6] += f3.x; acc[7] += f3.y;
            }
        }
        s += nb;
    }
    float* p = agg + (size_t)w * DF + lane * 8;
    *(float4*)(p)     = make_float4(acc[0], acc[1], acc[2], acc[3]);
    *(float4*)(p + 4) = make_float4(acc[4], acc[5], acc[6], acc[7]);
}

// ---------------------------------------------------------------------------
// Fused weight prep (one launch): Wt[n][k] = fp16(k<256 ? Ws[k][n] : Wn[..])
// ---------------------------------------------------------------------------
__global__ void convert_weights_all(
    const float* __restrict__ Ws0, const float* __restrict__ Wn0,
    const float* __restrict__ Ws1, const float* __restrict__ Wn1,
    const float* __restrict__ Ws2, const float* __restrict__ Wn2,
    __half* __restrict__ wt0, __half* __restrict__ wt1,
    __half* __restrict__ wt2)
{
    int idx = blockIdx.x * blockDim.x + threadIdx.x;
    const float *Ws, *Wn;
    __half* wt;
    int NC, local;
    if (idx < 131072)      { Ws = Ws0; Wn = Wn0; wt = wt0; NC = 256; local = idx; }
    else if (idx < 262144) { Ws = Ws1; Wn = Wn1; wt = wt1; NC = 256; local = idx - 131072; }
    else if (idx < 294912) { Ws = Ws2; Wn = Wn2; wt = wt2; NC = 64;  local = idx - 262144; }
    else return;
    int n = local >> 9, k = local & 511;
    float v = (k < 256) ? Ws[(size_t)k * NC + n] : Wn[(size_t)(k - 256) * NC + n];
    wt[local] = __float2half_rn(v);
}

// ---------------------------------------------------------------------------
// L1/L2 edge aggregation (unchanged): 4 edges/warp, gather + vector REDs.
// RELU: apply fmaxf(x,0) to gathered values (deferred layer-1 activation).
// ---------------------------------------------------------------------------
template<bool RELU>
__global__ void sage_aggregate(const float* __restrict__ h,
                               const int*   __restrict__ src,
                               const int*   __restrict__ dst,
                               float*       __restrict__ agg,
                               float*       __restrict__ deg,
                               int E)
{
    int warp = (int)(blockIdx.x * (blockDim.x >> 5) + (threadIdx.x >> 5));
    int lane = threadIdx.x & 31;
    int e0 = warp * 4;
    if (e0 >= E) return;
    int n = E - e0;
    if (n > 4) n = 4;

    int s[4], d[4];
#pragma unroll
    for (int e = 0; e < 4; e++) {
        int idx = (e < n) ? e0 + e : e0;
        s[e] = __ldg(src + idx);
        d[e] = __ldg(dst + idx);
    }
    float4 v[4][2];
#pragma unroll
    for (int e = 0; e < 4; e++) {
        if (e < n) {
            const float4* hs = (const float4*)(h + (size_t)s[e] * DF) + lane;
            v[e][0] = __ldg(hs);
            v[e][1] = __ldg(hs + 32);
            if (RELU) {
#pragma unroll
                for (int q = 0; q < 2; q++) {
                    v[e][q].x = fmaxf(v[e][q].x, 0.f);
                    v[e][q].y = fmaxf(v[e][q].y, 0.f);
                    v[e][q].z = fmaxf(v[e][q].z, 0.f);
                    v[e][q].w = fmaxf(v[e][q].w, 0.f);
                }
            }
        }
    }
#pragma unroll
    for (int e = 0; e < 4; e++) {
        if (e < n) {
            float* p = agg + (size_t)d[e] * DF + lane * 4;
            asm volatile("red.global.add.v4.f32 [%0], {%1, %2, %3, %4};"
                         :: "l"(p), "f"(v[e][0].x), "f"(v[e][0].y),
                            "f"(v[e][0].z), "f"(v[e][0].w) : "memory");
            asm volatile("red.global.add.v4.f32 [%0], {%1, %2, %3, %4};"
                         :: "l"(p + 128), "f"(v[e][1].x), "f"(v[e][1].y),
                            "f"(v[e][1].z), "f"(v[e][1].w) : "memory");
        }
    }
#pragma unroll
    for (int e = 0; e < 4; e++)
        if (lane == e && e < n) atomicAdd(deg + d[e], 1.0f);
}

// ---------------------------------------------------------------------------
// GEMM tile: CTA 128xBN, BK=64, 8 warps (4Mx2N), warp 32x(BN/2).
//   NEIGH: red.global.add  invd[m]*(agg@Wn)[m,n]  into out (no output read)
//   !NEIGH: out = relu?(A)@Ws + bias   (RELUA applies fmaxf to A on load)
// A fp32 -> regs -> fp16 smem (pitch 144 = 128B data + 16B skew).
// B fp16 via cp.async, double-buffered; 4 barrier iterations.
// ---------------------------------------------------------------------------
template<int BN, bool NEIGH, bool RELUA>
__device__ __forceinline__ void gemm_tile(
    const float* __restrict__ A, const float* __restrict__ deg,
    const __half* __restrict__ wt, int koff,
    const float* __restrict__ bias, float* __restrict__ out,
    int M, int NCOLS, int bm0, int bn0, char* smem)
{
    constexpr int APITCH = 144;
    constexpr int ASTG   = 128 * APITCH;
    constexpr int BSTG   = BN * APITCH;
    constexpr int SS     = ASTG + BSTG;
    constexpr int NT8    = BN / 16;
    constexpr int NBSEG  = BN / 32;
    constexpr int WN     = BN / 2;

    float* s_invd = (float*)smem;
    char*  stg    = smem + 1024;
    uint32_t stg_u = smem_u32(stg);

    int tid  = threadIdx.x;
    int lane = tid & 31, wid = tid >> 5;
    int wm = wid & 3, wn = wid >> 2;

    if (NEIGH) {
        if (tid < 128) {
            int r = bm0 + tid;
            float dg = (r < M) ? deg[r] : 1.0f;
            s_invd[tid] = 1.0f / fmaxf(dg, 1.0f);
        }
        __syncthreads();
    }

    uint4 ah[4];

    auto prepA = [&](int kt) {
        int kc = kt * 64;
#pragma unroll
        for (int i = 0; i < 4; i++) {
            int seg = tid + 256 * i;
            int row = seg >> 3, c8 = (seg & 7) * 8;
            int gr = bm0 + row;
            float4 v0 = make_float4(0.f, 0.f, 0.f, 0.f), v1 = v0;
            if (gr < M) {
                const float4* p = (const float4*)(A + (size_t)gr * DF + kc + c8);
                v0 = __ldg(p); v1 = __ldg(p + 1);
                if (RELUA) {
                    v0.x = fmaxf(v0.x, 0.f); v0.y = fmaxf(v0.y, 0.f);
                    v0.z = fmaxf(v0.z, 0.f); v0.w = fmaxf(v0.w, 0.f);
                    v1.x = fmaxf(v1.x, 0.f); v1.y = fmaxf(v1.y, 0.f);
                    v1.z = fmaxf(v1.z, 0.f); v1.w = fmaxf(v1.w, 0.f);
                }
            }
            ah[i] = cvt8(v0, v1);
        }
    };

    auto storeA = [&](int s) {
        char* base = stg + s * SS;
#pragma unroll
        for (int i = 0; i < 4; i++) {
            int seg = tid + 256 * i;
            int row = seg >> 3, cc = (seg & 7) * 16;
            *(uint4*)(base + row * APITCH + cc) = ah[i];
        }
    };

    auto issueB = [&](int kt, int s) {
        int kg = kt * 64;
        uint32_t bbase = stg_u + s * SS + ASTG;
#pragma unroll
        for (int i = 0; i < NBSEG; i++) {
            int seg = tid + 256 * i;
            int row = seg >> 3, cc = (seg & 7) * 16;
            uint32_t sa = bbase + row * APITCH + cc;
            const __half* g = wt + (size_t)(bn0 + row) * 512 + koff + kg + (seg & 7) * 8;
            asm volatile("cp.async.cg.shared.global [%0], [%1], 16;"
                         :: "r"(sa), "l"(g));
        }
        asm volatile("cp.async.commit_group;" ::: "memory");
    };

    float acc[2][NT8][4] = {};

    issueB(0, 0);
    prepA(0);

#pragma unroll 1
    for (int kt = 0; kt < 4; kt++) {
        int s = kt & 1;
        storeA(s);
        asm volatile("cp.async.wait_group 0;" ::: "memory");
        __syncthreads();
        if (kt < 3) {
            issueB(kt + 1, 1 - s);
            prepA(kt + 1);
        }

        uint32_t abase = stg_u + s * SS;
        uint32_t bbase = abase + ASTG;
#pragma unroll
        for (int ks = 0; ks < 4; ks++) {
            uint32_t af[2][4], bf[NT8][2];
#pragma unroll
            for (int mt = 0; mt < 2; mt++) {
                int r  = wm * 32 + mt * 16 + (lane & 7) + ((lane >> 3) & 1) * 8;
                int kb = ks * 16 + ((lane >> 4) & 1) * 8;
                ldsm4(af[mt], abase + r * APITCH + kb * 2);
            }
#pragma unroll
            for (int p = 0; p < NT8 / 2; p++) {
                int n  = wn * WN + p * 16 + (lane & 7) + ((lane >> 4) & 1) * 8;
                int kb = ks * 16 + ((lane >> 3) & 1) * 8;
                uint32_t th[4];
                ldsm4(th, bbase + n * APITCH + kb * 2);
                bf[2 * p][0] = th[0]; bf[2 * p][1] = th[1];
                bf[2 * p + 1][0] = th[2]; bf[2 * p + 1][1] = th[3];
            }
#pragma unroll
            for (int mt = 0; mt < 2; mt++)
#pragma unroll
                for (int nt = 0; nt < NT8; nt++)
                    mma16816(acc[mt][nt], af[mt], bf[nt]);
        }
    }

    // ---- epilogue ----
#pragma unroll
    for (int mt = 0; mt < 2; mt++) {
        int rr = wm * 32 + mt * 16 + (lane >> 2);
        int r0 = bm0 + rr;
        float sc0 = NEIGH ? s_invd[rr]     : 0.f;
        float sc1 = NEIGH ? s_invd[rr + 8] : 0.f;
#pragma unroll
        for (int nt = 0; nt < NT8; nt++) {
            int col = bn0 + wn * WN + nt * 8 + (lane & 3) * 2;
            if (NEIGH) {
                float o0x = acc[mt][nt][0] * sc0, o0y = acc[mt][nt][1] * sc0;
                float o1x = acc[mt][nt][2] * sc1, o1y = acc[mt][nt][3] * sc1;
                if (r0 < M) {
                    float* p = out + (size_t)r0 * NCOLS + col;
                    asm volatile("red.global.add.v2.f32 [%0], {%1, %2};"
                                 :: "l"(p), "f"(o0x), "f"(o0y) : "memory");
                }
                if (r0 + 8 < M) {
                    float* p = out + (size_t)(r0 + 8) * NCOLS + col;
                    asm volatile("red.global.add.v2.f32 [%0], {%1, %2};"
                                 :: "l"(p), "f"(o1x), "f"(o1y) : "memory");
                }
            } else {
                float2 bv = *(const float2*)(bias + col);
                float2 o0, o1;
                o0.x = acc[mt][nt][0] + bv.x; o0.y = acc[mt][nt][1] + bv.y;
                o1.x = acc[mt][nt][2] + bv.x; o1.y = acc[mt][nt][3] + bv.y;
                if (r0 < M)
                    *(float2*)(out + (size_t)r0 * NCOLS + col) = o0;
                if (r0 + 8 < M)
                    *(float2*)(out + (size_t)(r0 + 8) * NCOLS + col) = o1;
            }
        }
    }
}

template<int BN, bool RELUA>
__global__ __launch_bounds__(256)
void sage_gemm_self(const float* __restrict__ h,
                    const __half* __restrict__ wt,
                    const float* __restrict__ bias,
                    float* __restrict__ out, int M, int NCOLS)
{
    extern __shared__ char smem[];
    gemm_tile<BN, false, RELUA>(h, nullptr, wt, 0, bias, out, M, NCOLS,
                                blockIdx.y * 128, blockIdx.x * BN, smem);
}

template<int BN>
__global__ __launch_bounds__(256)
void sage_gemm_neigh(const float* __restrict__ agg,
                     const float* __restrict__ deg,
                     const __half* __restrict__ wt,
                     float* __restrict__ out, int M, int NCOLS)
{
    extern __shared__ char smem[];
    gemm_tile<BN, true, false>(agg, deg, wt, 256, nullptr, out, M, NCOLS,
                               blockIdx.y * 128, blockIdx.x * BN, smem);
}

// ---------------------------------------------------------------------------
// Launch
// ---------------------------------------------------------------------------
extern "C" void kernel_launch(void* const* d_in, const int* in_sizes, int n_in,
                              void* d_out, int out_size)
{
    const float* x    = (const float*)d_in[0];
    const int*   src0 = (const int*)d_in[1];
    const int*   dst0 = (const int*)d_in[2];
    const int*   src1 = (const int*)d_in[3];
    const int*   dst1 = (const int*)d_in[4];
    const int*   src2 = (const int*)d_in[5];
    const int*   dst2 = (const int*)d_in[6];

    int wb = n_in - 9;
    const float* Ws0 = (const float*)d_in[wb + 0];
    const float* Wn0 = (const float*)d_in[wb + 1];
    const float* b0  = (const float*)d_in[wb + 2];
    const float* Ws1 = (const float*)d_in[wb + 3];
    const float* Wn1 = (const float*)d_in[wb + 4];
    const float* b1  = (const float*)d_in[wb + 5];
    const float* Ws2 = (const float*)d_in[wb + 6];
    const float* Wn2 = (const float*)d_in[wb + 7];
    const float* b2  = (const float*)d_in[wb + 8];

    int E0 = in_sizes[1];
    int E1 = in_sizes[3];
    int E2 = in_sizes[5];
    int xN = in_sizes[0];   // N0*256

    float *scr, *h1, *h2, *agg0, *degf;
    int *cnt, *off, *cur, *ssrc;
    __half *x16, *wt0, *wt1, *wt2;
    cudaGetSymbolAddress((void**)&scr,  g_scr);
    cudaGetSymbolAddress((void**)&h1,   g_h1);
    cudaGetSymbolAddress((void**)&h2,   g_h2);
    cudaGetSymbolAddress((void**)&agg0, g_agg0);
    cudaGetSymbolAddress((void**)&degf, g_degf);
    cudaGetSymbolAddress((void**)&cnt,  g_cnt);
    cudaGetSymbolAddress((void**)&off,  g_off);
    cudaGetSymbolAddress((void**)&cur,  g_cur);
    cudaGetSymbolAddress((void**)&ssrc, g_ssrc);
    cudaGetSymbolAddress((void**)&x16,  g_x16);
    cudaGetSymbolAddress((void**)&wt0,  g_wt0);
    cudaGetSymbolAddress((void**)&wt1,  g_wt1);
    cudaGetSymbolAddress((void**)&wt2,  g_wt2);

    float* agg1 = scr + AGG1_OFF;
    float* deg1 = scr + DEG1_OFF;
    float* agg2 = scr + AGG2_OFF;
    float* deg2 = scr + DEG2_OFF;

    const int SMEM128 = 1024 + 2 * (18432 + 128 * 144);  // 74752
    const int SMEM64  = 1024 + 2 * (18432 + 64 * 144);   // 56320
    cudaFuncSetAttribute(sage_gemm_self<128, false>,
                         cudaFuncAttributeMaxDynamicSharedMemorySize, SMEM128);
    cudaFuncSetAttribute(sage_gemm_self<64, true>,
                         cudaFuncAttributeMaxDynamicSharedMemorySize, SMEM64);
    cudaFuncSetAttribute(sage_gemm_neigh<128>,
                         cudaFuncAttributeMaxDynamicSharedMemorySize, SMEM128);
    cudaFuncSetAttribute(sage_gemm_neigh<64>,
                         cudaFuncAttributeMaxDynamicSharedMemorySize, SMEM64);

    cudaStream_t s2;
    cudaStreamCreateWithFlags(&s2, cudaStreamNonBlocking);
    cudaEvent_t evStart, evX, evJ0, evJ1, evJ2, evN0, evN1;
    cudaEventCreateWithFlags(&evStart, cudaEventDisableTiming);
    cudaEventCreateWithFlags(&evX,     cudaEventDisableTiming);
    cudaEventCreateWithFlags(&evJ0,    cudaEventDisableTiming);
    cudaEventCreateWithFlags(&evJ1,    cudaEventDisableTiming);
    cudaEventCreateWithFlags(&evJ2,    cudaEventDisableTiming);
    cudaEventCreateWithFlags(&evN0,    cudaEventDisableTiming);
    cudaEventCreateWithFlags(&evN1,    cudaEventDisableTiming);

    // fork
    cudaEventRecord(evStart, 0);
    cudaStreamWaitEvent(s2, evStart, 0);

    // default: zero cnt, group L0 edges by dst
    cudaMemsetAsync(cnt, 0, sizeof(int) * N1C);
    deg_hist<<<(E0 + 255) / 256, 256>>>(dst0, E0, cnt);
    deg_scan<<<1, 1024>>>(cnt, off, cur, degf, E0);
    edge_scatter0<<<(E0 + 255) / 256, 256>>>(src0, dst0, E0, cur, ssrc);

    // s2: L1/L2 scratch zero, weights, x16 mirror, self0
    cudaMemsetAsync(scr, 0, sizeof(float) * (size_t)SCR_TOT, s2);
    convert_weights_all<<<(294912 + 255) / 256, 256, 0, s2>>>(
        Ws0, Wn0, Ws1, Wn1, Ws2, Wn2, wt0, wt1, wt2);
    convert_fp16<<<(xN / 8 + 255) / 256, 256, 0, s2>>>(x, x16, xN / 8);
    cudaEventRecord(evX, s2);
    sage_gemm_self<128, false><<<dim3(2, (N1C + 127) / 128), 256, SMEM128, s2>>>(
        x, wt0, b0, h1, N1C, 256);
    cudaEventRecord(evJ0, s2);

    // ---- Layer 0: grouped aggregate (needs x16 + scatter) ----
    cudaStreamWaitEvent(0, evX, 0);
    sage_agg0_grouped<<<(N1C + 7) / 8, 256>>>(x16, ssrc, off, agg0);
    cudaStreamWaitEvent(0, evJ0, 0);
    sage_gemm_neigh<128><<<dim3(2, (N1C + 127) / 128), 256, SMEM128>>>(
        agg0, degf, wt0, h1, N1C, 256);
    cudaEventRecord(evN0, 0);

    // s2: self1 after h1 complete
    cudaStreamWaitEvent(s2, evN0, 0);
    sage_gemm_self<128, false><<<dim3(2, (N2C + 127) / 128), 256, SMEM128, s2>>>(
        h1, wt1, b1, h2, N2C, 256);
    cudaEventRecord(evJ1, s2);

    // ---- Layer 1 (h2 stored pre-relu; consumers apply relu) ----
    sage_aggregate<false><<<(E1 + 31) / 32, 256>>>(h1, src1, dst1, agg1, deg1, E1);
    cudaStreamWaitEvent(0, evJ1, 0);
    sage_gemm_neigh<128><<<dim3(2, (N2C + 127) / 128), 256, SMEM128>>>(
        agg1, deg1, wt1, h2, N2C, 256);
    cudaEventRecord(evN1, 0);

    // s2: self2 after h2 complete (relu applied on A load)
    cudaStreamWaitEvent(s2, evN1, 0);
    sage_gemm_self<64, true><<<dim3(1, (N3C + 127) / 128), 256, SMEM64, s2>>>(
        h2, wt2, b2, (float*)d_out, N3C, 64);
    cudaEventRecord(evJ2, s2);

    // ---- Layer 2 (relu applied on gather) ----
    sage_aggregate<true><<<(E2 + 31) / 32, 256>>>(h2, src2, dst2, agg2, deg2, E2);
    cudaStreamWaitEvent(0, evJ2, 0);   // self2 wrote d_out base; RED adds after
    sage_gemm_neigh<64><<<dim3(1, (N3C + 127) / 128), 256, SMEM64>>>(
        agg2, deg2, wt2, (float*)d_out, N3C, 64);
}

// round 14
// speedup vs baseline: 1.0263x; 1.0263x over previous
#include <cuda_runtime.h>
#include <cuda_fp16.h>
#include <cstdint>

// ---------------------------------------------------------------------------
// SAGE_37203006718147: 3-layer GraphSAGE on sm_103a.
// L0 aggregation: edges grouped by dst (hist -> 50k scan -> scatter of src
// ids), then warp-per-dst gather of fp32 x with fp32 register accumulation
// -> agg0 rows written ONCE (no feature REDs, no agg0/deg0 memset, deg free).
// Per layer (fork-join on two captured streams):
//   [default] aggregation   ||  [s2] self-GEMM
//   join -> [default] neigh-GEMM: RED-accumulate invd[m]*(agg@Wn) into out
// relu (layer-1 output) deferred to the consumers of h2 (exact).
// GEMM: mma.sync fp16 1-term, fp32 accumulate, BK=64, CTA tile 128x128.
// tcgen05 unavailable: harness compiles at virtual arch compute_103 (no 'a').
// ---------------------------------------------------------------------------

#define N0C 200000
#define N1C 50000
#define N2C 12000
#define N3C 3000
#define DF  256
#define E0MAX 500000

// ---- L0 grouping scratch ----
__device__ int    g_cnt [N1C];
__device__ int    g_off [N1C + 1];
__device__ int    g_cur [N1C];
__device__ float  g_degf[N1C];
__device__ int    g_ssrc[E0MAX];
__device__ float  g_agg0[N1C * DF];
// ---- L1/L2 scratch (one memset on s2): agg1|deg1|agg2|deg2 ----
#define AGG1_OFF 0
#define DEG1_OFF (N2C * DF)
#define AGG2_OFF (DEG1_OFF + N2C)
#define DEG2_OFF (AGG2_OFF + N3C * DF)
#define SCR_TOT  (DEG2_OFF + N3C)
__device__ float  g_scr[SCR_TOT];
__device__ float  g_h1 [N1C * DF];
__device__ float  g_h2 [N2C * DF];
// transposed fp16 weights: [N][K=512] = [Ws ; Wn], K-major
__device__ __half g_wt0[256 * 512];
__device__ __half g_wt1[256 * 512];
__device__ __half g_wt2[64 * 512];

// ---------------------------------------------------------------------------
// helpers
// ---------------------------------------------------------------------------
__device__ __forceinline__ uint32_t smem_u32(const void* p) {
    uint32_t a;
    asm("{ .reg .u64 t; cvta.to.shared.u64 t, %1; cvt.u32.u64 %0, t; }"
        : "=r"(a) : "l"(p));
    return a;
}

__device__ __forceinline__ void ldsm4(uint32_t* r, uint32_t addr) {
    asm volatile("ldmatrix.sync.aligned.m8n8.x4.shared.b16 {%0,%1,%2,%3}, [%4];"
                 : "=r"(r[0]), "=r"(r[1]), "=r"(r[2]), "=r"(r[3]) : "r"(addr));
}

__device__ __forceinline__ void mma16816(float* c, const uint32_t* a,
                                         const uint32_t* b) {
    asm volatile(
        "mma.sync.aligned.m16n8k16.row.col.f32.f16.f16.f32 "
        "{%0,%1,%2,%3}, {%4,%5,%6,%7}, {%8,%9}, {%0,%1,%2,%3};"
        : "+f"(c[0]), "+f"(c[1]), "+f"(c[2]), "+f"(c[3])
        : "r"(a[0]), "r"(a[1]), "r"(a[2]), "r"(a[3]), "r"(b[0]), "r"(b[1]));
}

// convert 8 fp32 -> 8 packed fp16 (uint4)
__device__ __forceinline__ uint4 cvt8(float4 a, float4 b) {
    float f[8] = {a.x, a.y, a.z, a.w, b.x, b.y, b.z, b.w};
    uint32_t H[8];
#pragma unroll
    for (int i = 0; i < 8; i++)
        H[i] = (uint32_t)__half_as_ushort(__float2half_rn(f[i]));
    uint4 r;
    r.x = H[0] | (H[1] << 16); r.y = H[2] | (H[3] << 16);
    r.z = H[4] | (H[5] << 16); r.w = H[6] | (H[7] << 16);
    return r;
}

// ---------------------------------------------------------------------------
// L0 dst-grouping: count -> scan(50k, single block) -> scatter src ids
// ---------------------------------------------------------------------------
__global__ void deg_hist(const int* __restrict__ dst, int E,
                         int* __restrict__ cnt)
{
    int i = blockIdx.x * blockDim.x + threadIdx.x;
    if (i < E) atomicAdd(&cnt[__ldg(dst + i)], 1);
}

__global__ void deg_scan(const int* __restrict__ cnt,
                         int* __restrict__ off, int* __restrict__ cur,
                         float* __restrict__ degf, int E)
{
    __shared__ int tot[1024];
    const int C = (N1C + 1023) / 1024;   // 49
    int t = threadIdx.x;
    int base = t * C;
    int sum = 0;
#pragma unroll 1
    for (int i = 0; i < C; i++) {
        int idx = base + i;
        if (idx < N1C) sum += __ldg(cnt + idx);
    }
    tot[t] = sum;
    __syncthreads();
#pragma unroll
    for (int o = 1; o < 1024; o <<= 1) {
        int u = (t >= o) ? tot[t - o] : 0;
        __syncthreads();
        tot[t] += u;
        __syncthreads();
    }
    int run = tot[t] - sum;   // exclusive prefix for this thread's chunk
#pragma unroll 1
    for (int i = 0; i < C; i++) {
        int idx = base + i;
        if (idx < N1C) {
            int v = __ldg(cnt + idx);
            off[idx]  = run;
            cur[idx]  = run;
            degf[idx] = (float)v;
            run += v;
        }
    }
    if (t == 1023) off[N1C] = E;
}

__global__ void edge_scatter0(const int* __restrict__ src,
                              const int* __restrict__ dst, int E,
                              int* __restrict__ cur, int* __restrict__ ssrc)
{
    int i = blockIdx.x * blockDim.x + threadIdx.x;
    if (i >= E) return;
    int pos = atomicAdd(&cur[__ldg(dst + i)], 1);
    ssrc[pos] = __ldg(src + i);
}

// ---------------------------------------------------------------------------
// L0 aggregate: one warp per dst node. Gather fp32 rows (2 float4/lane/row),
// accumulate fp32 in registers, write the agg row once. No feature atomics.
// ---------------------------------------------------------------------------
__global__ void sage_agg0_grouped(const float* __restrict__ x,
                                  const int* __restrict__ ssrc,
                                  const int* __restrict__ off,
                                  float* __restrict__ agg)
{
    int w = (int)(blockIdx.x * (blockDim.x >> 5) + (threadIdx.x >> 5));
    if (w >= N1C) return;
    int lane = threadIdx.x & 31;
    int s = __ldg(off + w), e = __ldg(off + w + 1);

    float acc[8] = {};
#pragma unroll 1
    while (s < e) {
        int nb = e - s;
        if (nb > 4) nb = 4;
        float4 v[4][2];
#pragma unroll
        for (int b = 0; b < 4; b++) {
            if (b < nb) {
                int row = __ldg(ssrc + s + b);
                const float4* p = (const float4*)(x + (size_t)row * DF) + lane * 2;
                v[b][0] = __ldg(p);
                v[b][1] = __ldg(p + 1);
            }
        }
#pragma unroll
        for (int b = 0; b < 4; b++) {
            if (b < nb) {
                acc[0] += v[b][0].x; acc[1] += v[b][0].y;
                acc[2] += v[b][0].z; acc[3] += v[b][0].w;
                acc[4] += v[b][1].x; acc[5] += v[b][1].y;
                acc[6] += v[b][1].z; acc[7] += v[b][1].w;
            }
        }
        s += nb;
    }
    float* p = agg + (size_t)w * DF + lane * 8;
    *(float4*)(p)     = make_float4(acc[0], acc[1], acc[2], acc[3]);
    *(float4*)(p + 4) = make_float4(acc[4], acc[5], acc[6], acc[7]);
}

// ---------------------------------------------------------------------------
// Fused weight prep (one launch): Wt[n][k] = fp16(k<256 ? Ws[k][n] : Wn[..])
// ---------------------------------------------------------------------------
__global__ void convert_weights_all(
    const float* __restrict__ Ws0, const float* __restrict__ Wn0,
    const float* __restrict__ Ws1, const float* __restrict__ Wn1,
    const float* __restrict__ Ws2, const float* __restrict__ Wn2,
    __half* __restrict__ wt0, __half* __restrict__ wt1,
    __half* __restrict__ wt2)
{
    int idx = blockIdx.x * blockDim.x + threadIdx.x;
    const float *Ws, *Wn;
    __half* wt;
    int NC, local;
    if (idx < 131072)      { Ws = Ws0; Wn = Wn0; wt = wt0; NC = 256; local = idx; }
    else if (idx < 262144) { Ws = Ws1; Wn = Wn1; wt = wt1; NC = 256; local = idx - 131072; }
    else if (idx < 294912) { Ws = Ws2; Wn = Wn2; wt = wt2; NC = 64;  local = idx - 262144; }
    else return;
    int n = local >> 9, k = local & 511;
    float v = (k < 256) ? Ws[(size_t)k * NC + n] : Wn[(size_t)(k - 256) * NC + n];
    wt[local] = __float2half_rn(v);
}

// ---------------------------------------------------------------------------
// L1/L2 edge aggregation: 4 edges/warp, gather + vector REDs.
// RELU: apply fmaxf(x,0) to gathered values (deferred layer-1 activation).
// ---------------------------------------------------------------------------
template<bool RELU>
__global__ void sage_aggregate(const float* __restrict__ h,
                               const int*   __restrict__ src,
                               const int*   __restrict__ dst,
                               float*       __restrict__ agg,
                               float*       __restrict__ deg,
                               int E)
{
    int warp = (int)(blockIdx.x * (blockDim.x >> 5) + (threadIdx.x >> 5));
    int lane = threadIdx.x & 31;
    int e0 = warp * 4;
    if (e0 >= E) return;
    int n = E - e0;
    if (n > 4) n = 4;

    int s[4], d[4];
#pragma unroll
    for (int e = 0; e < 4; e++) {
        int idx = (e < n) ? e0 + e : e0;
        s[e] = __ldg(src + idx);
        d[e] = __ldg(dst + idx);
    }
    float4 v[4][2];
#pragma unroll
    for (int e = 0; e < 4; e++) {
        if (e < n) {
            const float4* hs = (const float4*)(h + (size_t)s[e] * DF) + lane;
            v[e][0] = __ldg(hs);
            v[e][1] = __ldg(hs + 32);
            if (RELU) {
#pragma unroll
                for (int q = 0; q < 2; q++) {
                    v[e][q].x = fmaxf(v[e][q].x, 0.f);
                    v[e][q].y = fmaxf(v[e][q].y, 0.f);
                    v[e][q].z = fmaxf(v[e][q].z, 0.f);
                    v[e][q].w = fmaxf(v[e][q].w, 0.f);
                }
            }
        }
    }
#pragma unroll
    for (int e = 0; e < 4; e++) {
        if (e < n) {
            float* p = agg + (size_t)d[e] * DF + lane * 4;
            asm volatile("red.global.add.v4.f32 [%0], {%1, %2, %3, %4};"
                         :: "l"(p), "f"(v[e][0].x), "f"(v[e][0].y),
                            "f"(v[e][0].z), "f"(v[e][0].w) : "memory");
            asm volatile("red.global.add.v4.f32 [%0], {%1, %2, %3, %4};"
                         :: "l"(p + 128), "f"(v[e][1].x), "f"(v[e][1].y),
                            "f"(v[e][1].z), "f"(v[e][1].w) : "memory");
        }
    }
#pragma unroll
    for (int e = 0; e < 4; e++)
        if (lane == e && e < n) atomicAdd(deg + d[e], 1.0f);
}

// ---------------------------------------------------------------------------
// GEMM tile: CTA 128xBN, BK=64, 8 warps (4Mx2N), warp 32x(BN/2).
//   NEIGH: red.global.add  invd[m]*(agg@Wn)[m,n]  into out (no output read)
//   !NEIGH: out = relu?(A)@Ws + bias   (RELUA applies fmaxf to A on load)
// A fp32 -> regs -> fp16 smem (pitch 144 = 128B data + 16B skew).
// B fp16 via cp.async, double-buffered; 4 barrier iterations.
// ---------------------------------------------------------------------------
template<int BN, bool NEIGH, bool RELUA>
__device__ __forceinline__ void gemm_tile(
    const float* __restrict__ A, const float* __restrict__ deg,
    const __half* __restrict__ wt, int koff,
    const float* __restrict__ bias, float* __restrict__ out,
    int M, int NCOLS, int bm0, int bn0, char* smem)
{
    constexpr int APITCH = 144;
    constexpr int ASTG   = 128 * APITCH;
    constexpr int BSTG   = BN * APITCH;
    constexpr int SS     = ASTG + BSTG;
    constexpr int NT8    = BN / 16;
    constexpr int NBSEG  = BN / 32;
    constexpr int WN     = BN / 2;

    float* s_invd = (float*)smem;
    char*  stg    = smem + 1024;
    uint32_t stg_u = smem_u32(stg);

    int tid  = threadIdx.x;
    int lane = tid & 31, wid = tid >> 5;
    int wm = wid & 3, wn = wid >> 2;

    if (NEIGH) {
        if (tid < 128) {
            int r = bm0 + tid;
            float dg = (r < M) ? deg[r] : 1.0f;
            s_invd[tid] = 1.0f / fmaxf(dg, 1.0f);
        }
        __syncthreads();
    }

    uint4 ah[4];

    auto prepA = [&](int kt) {
        int kc = kt * 64;
#pragma unroll
        for (int i = 0; i < 4; i++) {
            int seg = tid + 256 * i;
            int row = seg >> 3, c8 = (seg & 7) * 8;
            int gr = bm0 + row;
            float4 v0 = make_float4(0.f, 0.f, 0.f, 0.f), v1 = v0;
            if (gr < M) {
                const float4* p = (const float4*)(A + (size_t)gr * DF + kc + c8);
                v0 = __ldg(p); v1 = __ldg(p + 1);
                if (RELUA) {
                    v0.x = fmaxf(v0.x, 0.f); v0.y = fmaxf(v0.y, 0.f);
                    v0.z = fmaxf(v0.z, 0.f); v0.w = fmaxf(v0.w, 0.f);
                    v1.x = fmaxf(v1.x, 0.f); v1.y = fmaxf(v1.y, 0.f);
                    v1.z = fmaxf(v1.z, 0.f); v1.w = fmaxf(v1.w, 0.f);
                }
            }
            ah[i] = cvt8(v0, v1);
        }
    };

    auto storeA = [&](int s) {
        char* base = stg + s * SS;
#pragma unroll
        for (int i = 0; i < 4; i++) {
            int seg = tid + 256 * i;
            int row = seg >> 3, cc = (seg & 7) * 16;
            *(uint4*)(base + row * APITCH + cc) = ah[i];
        }
    };

    auto issueB = [&](int kt, int s) {
        int kg = kt * 64;
        uint32_t bbase = stg_u + s * SS + ASTG;
#pragma unroll
        for (int i = 0; i < NBSEG; i++) {
            int seg = tid + 256 * i;
            int row = seg >> 3, cc = (seg & 7) * 16;
            uint32_t sa = bbase + row * APITCH + cc;
            const __half* g = wt + (size_t)(bn0 + row) * 512 + koff + kg + (seg & 7) * 8;
            asm volatile("cp.async.cg.shared.global [%0], [%1], 16;"
                         :: "r"(sa), "l"(g));
        }
        asm volatile("cp.async.commit_group;" ::: "memory");
    };

    float acc[2][NT8][4] = {};

    issueB(0, 0);
    prepA(0);

#pragma unroll 1
    for (int kt = 0; kt < 4; kt++) {
        int s = kt & 1;
        storeA(s);
        asm volatile("cp.async.wait_group 0;" ::: "memory");
        __syncthreads();
        if (kt < 3) {
            issueB(kt + 1, 1 - s);
            prepA(kt + 1);
        }

        uint32_t abase = stg_u + s * SS;
        uint32_t bbase = abase + ASTG;
#pragma unroll
        for (int ks = 0; ks < 4; ks++) {
            uint32_t af[2][4], bf[NT8][2];
#pragma unroll
            for (int mt = 0; mt < 2; mt++) {
                int r  = wm * 32 + mt * 16 + (lane & 7) + ((lane >> 3) & 1) * 8;
                int kb = ks * 16 + ((lane >> 4) & 1) * 8;
                ldsm4(af[mt], abase + r * APITCH + kb * 2);
            }
#pragma unroll
            for (int p = 0; p < NT8 / 2; p++) {
                int n  = wn * WN + p * 16 + (lane & 7) + ((lane >> 4) & 1) * 8;
                int kb = ks * 16 + ((lane >> 3) & 1) * 8;
                uint32_t th[4];
                ldsm4(th, bbase + n * APITCH + kb * 2);
                bf[2 * p][0] = th[0]; bf[2 * p][1] = th[1];
                bf[2 * p + 1][0] = th[2]; bf[2 * p + 1][1] = th[3];
            }
#pragma unroll
            for (int mt = 0; mt < 2; mt++)
#pragma unroll
                for (int nt = 0; nt < NT8; nt++)
                    mma16816(acc[mt][nt], af[mt], bf[nt]);
        }
    }

    // ---- epilogue ----
#pragma unroll
    for (int mt = 0; mt < 2; mt++) {
        int rr = wm * 32 + mt * 16 + (lane >> 2);
        int r0 = bm0 + rr;
        float sc0 = NEIGH ? s_invd[rr]     : 0.f;
        float sc1 = NEIGH ? s_invd[rr + 8] : 0.f;
#pragma unroll
        for (int nt = 0; nt < NT8; nt++) {
            int col = bn0 + wn * WN + nt * 8 + (lane & 3) * 2;
            if (NEIGH) {
                float o0x = acc[mt][nt][0] * sc0, o0y = acc[mt][nt][1] * sc0;
                float o1x = acc[mt][nt][2] * sc1, o1y = acc[mt][nt][3] * sc1;
                if (r0 < M) {
                    float* p = out + (size_t)r0 * NCOLS + col;
                    asm volatile("red.global.add.v2.f32 [%0], {%1, %2};"
                                 :: "l"(p), "f"(o0x), "f"(o0y) : "memory");
                }
                if (r0 + 8 < M) {
                    float* p = out + (size_t)(r0 + 8) * NCOLS + col;
                    asm volatile("red.global.add.v2.f32 [%0], {%1, %2};"
                                 :: "l"(p), "f"(o1x), "f"(o1y) : "memory");
                }
            } else {
                float2 bv = *(const float2*)(bias + col);
                float2 o0, o1;
                o0.x = acc[mt][nt][0] + bv.x; o0.y = acc[mt][nt][1] + bv.y;
                o1.x = acc[mt][nt][2] + bv.x; o1.y = acc[mt][nt][3] + bv.y;
                if (r0 < M)
                    *(float2*)(out + (size_t)r0 * NCOLS + col) = o0;
                if (r0 + 8 < M)
                    *(float2*)(out + (size_t)(r0 + 8) * NCOLS + col) = o1;
            }
        }
    }
}

template<int BN, bool RELUA>
__global__ __launch_bounds__(256)
void sage_gemm_self(const float* __restrict__ h,
                    const __half* __restrict__ wt,
                    const float* __restrict__ bias,
                    float* __restrict__ out, int M, int NCOLS)
{
    extern __shared__ char smem[];
    gemm_tile<BN, false, RELUA>(h, nullptr, wt, 0, bias, out, M, NCOLS,
                                blockIdx.y * 128, blockIdx.x * BN, smem);
}

template<int BN>
__global__ __launch_bounds__(256)
void sage_gemm_neigh(const float* __restrict__ agg,
                     const float* __restrict__ deg,
                     const __half* __restrict__ wt,
                     float* __restrict__ out, int M, int NCOLS)
{
    extern __shared__ char smem[];
    gemm_tile<BN, true, false>(agg, deg, wt, 256, nullptr, out, M, NCOLS,
                               blockIdx.y * 128, blockIdx.x * BN, smem);
}

// ---------------------------------------------------------------------------
// Launch
// ---------------------------------------------------------------------------
extern "C" void kernel_launch(void* const* d_in, const int* in_sizes, int n_in,
                              void* d_out, int out_size)
{
    const float* x    = (const float*)d_in[0];
    const int*   src0 = (const int*)d_in[1];
    const int*   dst0 = (const int*)d_in[2];
    const int*   src1 = (const int*)d_in[3];
    const int*   dst1 = (const int*)d_in[4];
    const int*   src2 = (const int*)d_in[5];
    const int*   dst2 = (const int*)d_in[6];

    int wb = n_in - 9;
    const float* Ws0 = (const float*)d_in[wb + 0];
    const float* Wn0 = (const float*)d_in[wb + 1];
    const float* b0  = (const float*)d_in[wb + 2];
    const float* Ws1 = (const float*)d_in[wb + 3];
    const float* Wn1 = (const float*)d_in[wb + 4];
    const float* b1  = (const float*)d_in[wb + 5];
    const float* Ws2 = (const float*)d_in[wb + 6];
    const float* Wn2 = (const float*)d_in[wb + 7];
    const float* b2  = (const float*)d_in[wb + 8];

    int E0 = in_sizes[1];
    int E1 = in_sizes[3];
    int E2 = in_sizes[5];

    float *scr, *h1, *h2, *agg0, *degf;
    int *cnt, *off, *cur, *ssrc;
    __half *wt0, *wt1, *wt2;
    cudaGetSymbolAddress((void**)&scr,  g_scr);
    cudaGetSymbolAddress((void**)&h1,   g_h1);
    cudaGetSymbolAddress((void**)&h2,   g_h2);
    cudaGetSymbolAddress((void**)&agg0, g_agg0);
    cudaGetSymbolAddress((void**)&degf, g_degf);
    cudaGetSymbolAddress((void**)&cnt,  g_cnt);
    cudaGetSymbolAddress((void**)&off,  g_off);
    cudaGetSymbolAddress((void**)&cur,  g_cur);
    cudaGetSymbolAddress((void**)&ssrc, g_ssrc);
    cudaGetSymbolAddress((void**)&wt0,  g_wt0);
    cudaGetSymbolAddress((void**)&wt1,  g_wt1);
    cudaGetSymbolAddress((void**)&wt2,  g_wt2);

    float* agg1 = scr + AGG1_OFF;
    float* deg1 = scr + DEG1_OFF;
    float* agg2 = scr + AGG2_OFF;
    float* deg2 = scr + DEG2_OFF;

    const int SMEM128 = 1024 + 2 * (18432 + 128 * 144);  // 74752
    const int SMEM64  = 1024 + 2 * (18432 + 64 * 144);   // 56320
    cudaFuncSetAttribute(sage_gemm_self<128, false>,
                         cudaFuncAttributeMaxDynamicSharedMemorySize, SMEM128);
    cudaFuncSetAttribute(sage_gemm_self<64, true>,
                         cudaFuncAttributeMaxDynamicSharedMemorySize, SMEM64);
    cudaFuncSetAttribute(sage_gemm_neigh<128>,
                         cudaFuncAttributeMaxDynamicSharedMemorySize, SMEM128);
    cudaFuncSetAttribute(sage_gemm_neigh<64>,
                         cudaFuncAttributeMaxDynamicSharedMemorySize, SMEM64);

    cudaStream_t s2;
    cudaStreamCreateWithFlags(&s2, cudaStreamNonBlocking);
    cudaEvent_t evStart, evJ0, evJ1, evJ2, evN0, evN1;
    cudaEventCreateWithFlags(&evStart, cudaEventDisableTiming);
    cudaEventCreateWithFlags(&evJ0,    cudaEventDisableTiming);
    cudaEventCreateWithFlags(&evJ1,    cudaEventDisableTiming);
    cudaEventCreateWithFlags(&evJ2,    cudaEventDisableTiming);
    cudaEventCreateWithFlags(&evN0,    cudaEventDisableTiming);
    cudaEventCreateWithFlags(&evN1,    cudaEventDisableTiming);

    // fork
    cudaEventRecord(evStart, 0);
    cudaStreamWaitEvent(s2, evStart, 0);

    // default: zero cnt, group L0 edges by dst, then grouped aggregate
    cudaMemsetAsync(cnt, 0, sizeof(int) * N1C);
    deg_hist<<<(E0 + 255) / 256, 256>>>(dst0, E0, cnt);
    deg_scan<<<1, 1024>>>(cnt, off, cur, degf, E0);
    edge_scatter0<<<(E0 + 255) / 256, 256>>>(src0, dst0, E0, cur, ssrc);

    // s2: L1/L2 scratch zero, weights, self0
    cudaMemsetAsync(scr, 0, sizeof(float) * (size_t)SCR_TOT, s2);
    convert_weights_all<<<(294912 + 255) / 256, 256, 0, s2>>>(
        Ws0, Wn0, Ws1, Wn1, Ws2, Wn2, wt0, wt1, wt2);
    sage_gemm_self<128, false><<<dim3(2, (N1C + 127) / 128), 256, SMEM128, s2>>>(
        x, wt0, b0, h1, N1C, 256);
    cudaEventRecord(evJ0, s2);

    // ---- Layer 0: grouped aggregate (fp32 x, no extra deps) ----
    sage_agg0_grouped<<<(N1C + 7) / 8, 256>>>(x, ssrc, off, agg0);
    cudaStreamWaitEvent(0, evJ0, 0);
    sage_gemm_neigh<128><<<dim3(2, (N1C + 127) / 128), 256, SMEM128>>>(
        agg0, degf, wt0, h1, N1C, 256);
    cudaEventRecord(evN0, 0);

    // s2: self1 after h1 complete
    cudaStreamWaitEvent(s2, evN0, 0);
    sage_gemm_self<128, false><<<dim3(2, (N2C + 127) / 128), 256, SMEM128, s2>>>(
        h1, wt1, b1, h2, N2C, 256);
    cudaEventRecord(evJ1, s2);

    // ---- Layer 1 (h2 stored pre-relu; consumers apply relu) ----
    sage_aggregate<false><<<(E1 + 31) / 32, 256>>>(h1, src1, dst1, agg1, deg1, E1);
    cudaStreamWaitEvent(0, evJ1, 0);
    sage_gemm_neigh<128><<<dim3(2, (N2C + 127) / 128), 256, SMEM128>>>(
        agg1, deg1, wt1, h2, N2C, 256);
    cudaEventRecord(evN1, 0);

    // s2: self2 after h2 complete (relu applied on A load)
    cudaStreamWaitEvent(s2, evN1, 0);
    sage_gemm_self<64, true><<<dim3(1, (N3C + 127) / 128), 256, SMEM64, s2>>>(
        h2, wt2, b2, (float*)d_out, N3C, 64);
    cudaEventRecord(evJ2, s2);

    // ---- Layer 2 (relu applied on gather) ----
    sage_aggregate<true><<<(E2 + 31) / 32, 256>>>(h2, src2, dst2, agg2, deg2, E2);
    cudaStreamWaitEvent(0, evJ2, 0);   // self2 wrote d_out base; RED adds after
    sage_gemm_neigh<64><<<dim3(1, (N3C + 127) / 128), 256, SMEM64>>>(
        agg2, deg2, wt2, (float*)d_out, N3C, 64);
}

// round 15
// speedup vs baseline: 1.2288x; 1.1973x over previous
#include <cuda_runtime.h>
#include <cuda_fp16.h>
#include <cstdint>

// ---------------------------------------------------------------------------
// SAGE_37203006718147: 3-layer GraphSAGE on sm_103a.  (R12 structure + the
// 51MB agg0/deg0 memset moved to s2, off the critical path.)
// L0 edges partitioned by src>>10 (CTA-aggregated radix pass) for gather
// locality. Per layer (fork-join on two captured streams):
//   [default] edge-aggregation (fp32 gather, vector RED)   ||  [s2] self-GEMM
//   join -> [default] neigh-GEMM: RED-accumulate invd[m]*(agg@Wn) into out
// relu (layer-1 output) deferred to the consumers of h2 (exact).
// GEMM: mma.sync fp16 1-term, fp32 accumulate, BK=64, CTA tile 128x128.
// tcgen05 unavailable: harness compiles at virtual arch compute_103 (no 'a').
// ---------------------------------------------------------------------------

#define N1C 50000
#define N2C 12000
#define N3C 3000
#define DF  256
#define E0MAX 500000
#define NBUK 256

// ---- contiguous scratch: hist | agg0|deg0 | agg1|deg1 | agg2|deg2 ----
#define HIST_OFF 0
#define AGG0_OFF NBUK
#define DEG0_OFF (AGG0_OFF + N1C * DF)
#define AGG1_OFF (DEG0_OFF + N1C)
#define DEG1_OFF (AGG1_OFF + N2C * DF)
#define AGG2_OFF (DEG1_OFF + N2C)
#define DEG2_OFF (AGG2_OFF + N3C * DF)
#define SCR_TOT  (DEG2_OFF + N3C)

__device__ float  g_scr[SCR_TOT];
__device__ float  g_h1 [N1C * DF];
__device__ float  g_h2 [N2C * DF];
__device__ int    g_bcur[NBUK];
__device__ int    g_ssrc[E0MAX];
__device__ int    g_sdst[E0MAX];
// transposed fp16 weights: [N][K=512] = [Ws ; Wn], K-major
__device__ __half g_wt0[256 * 512];
__device__ __half g_wt1[256 * 512];
__device__ __half g_wt2[64 * 512];

// ---------------------------------------------------------------------------
// helpers
// ---------------------------------------------------------------------------
__device__ __forceinline__ uint32_t smem_u32(const void* p) {
    uint32_t a;
    asm("{ .reg .u64 t; cvta.to.shared.u64 t, %1; cvt.u32.u64 %0, t; }"
        : "=r"(a) : "l"(p));
    return a;
}

__device__ __forceinline__ void ldsm4(uint32_t* r, uint32_t addr) {
    asm volatile("ldmatrix.sync.aligned.m8n8.x4.shared.b16 {%0,%1,%2,%3}, [%4];"
                 : "=r"(r[0]), "=r"(r[1]), "=r"(r[2]), "=r"(r[3]) : "r"(addr));
}

__device__ __forceinline__ void mma16816(float* c, const uint32_t* a,
                                         const uint32_t* b) {
    asm volatile(
        "mma.sync.aligned.m16n8k16.row.col.f32.f16.f16.f32 "
        "{%0,%1,%2,%3}, {%4,%5,%6,%7}, {%8,%9}, {%0,%1,%2,%3};"
        : "+f"(c[0]), "+f"(c[1]), "+f"(c[2]), "+f"(c[3])
        : "r"(a[0]), "r"(a[1]), "r"(a[2]), "r"(a[3]), "r"(b[0]), "r"(b[1]));
}

// convert 8 fp32 -> 8 packed fp16 (uint4)
__device__ __forceinline__ uint4 cvt8(float4 a, float4 b) {
    float f[8] = {a.x, a.y, a.z, a.w, b.x, b.y, b.z, b.w};
    uint32_t H[8];
#pragma unroll
    for (int i = 0; i < 8; i++)
        H[i] = (uint32_t)__half_as_ushort(__float2half_rn(f[i]));
    uint4 r;
    r.x = H[0] | (H[1] << 16); r.y = H[2] | (H[3] << 16);
    r.z = H[4] | (H[5] << 16); r.w = H[6] | (H[7] << 16);
    return r;
}

// ---------------------------------------------------------------------------
// L0 edge partition by src>>10: hist -> scan -> CTA-aggregated scatter
// ---------------------------------------------------------------------------
__global__ void edge_hist(const int* __restrict__ src, int E,
                          int* __restrict__ hist)
{
    __shared__ int sh[NBUK];
    int t = threadIdx.x;
    sh[t] = 0;
    __syncthreads();
    int base = blockIdx.x * 2048;
#pragma unroll
    for (int i = 0; i < 8; i++) {
        int idx = base + t + i * 256;
        if (idx < E) atomicAdd(&sh[__ldg(src + idx) >> 10], 1);
    }
    __syncthreads();
    if (sh[t]) atomicAdd(&hist[t], sh[t]);
}

__global__ void bucket_scan(const int* __restrict__ hist,
                            int* __restrict__ bcur)
{
    __shared__ int sh[NBUK];
    int t = threadIdx.x;
    int v = hist[t];
    sh[t] = v;
    __syncthreads();
#pragma unroll
    for (int o = 1; o < NBUK; o <<= 1) {
        int u = (t >= o) ? sh[t - o] : 0;
        __syncthreads();
        sh[t] += u;
        __syncthreads();
    }
    bcur[t] = sh[t] - v;   // exclusive prefix
}

// CTA-aggregated scatter: smem local ranks, ONE gmem atomic per (CTA,bucket)
__global__ void edge_partition(const int* __restrict__ src,
                               const int* __restrict__ dst, int E,
                               int* __restrict__ bcur,
                               int* __restrict__ ssrc,
                               int* __restrict__ sdst)
{
    __shared__ int scnt[NBUK];
    __shared__ int sbase[NBUK];
    int t = threadIdx.x;
    scnt[t] = 0;
    __syncthreads();
    int base = blockIdx.x * 2048;
    int s[8], d[8], bk[8], rk[8];
#pragma unroll
    for (int i = 0; i < 8; i++) {
        int idx = base + t + i * 256;
        if (idx < E) {
            s[i] = __ldg(src + idx);
            d[i] = __ldg(dst + idx);
            bk[i] = s[i] >> 10;
            rk[i] = atomicAdd(&scnt[bk[i]], 1);
        } else bk[i] = -1;
    }
    __syncthreads();
    int c = scnt[t];
    sbase[t] = c ? atomicAdd(&bcur[t], c) : 0;
    __syncthreads();
#pragma unroll
    for (int i = 0; i < 8; i++) {
        if (bk[i] >= 0) {
            int pos = sbase[bk[i]] + rk[i];
            ssrc[pos] = s[i];
            sdst[pos] = d[i];
        }
    }
}

// ---------------------------------------------------------------------------
// Fused weight prep (one launch): Wt[n][k] = fp16(k<256 ? Ws[k][n] : Wn[..])
// ---------------------------------------------------------------------------
__global__ void convert_weights_all(
    const float* __restrict__ Ws0, const float* __restrict__ Wn0,
    const float* __restrict__ Ws1, const float* __restrict__ Wn1,
    const float* __restrict__ Ws2, const float* __restrict__ Wn2,
    __half* __restrict__ wt0, __half* __restrict__ wt1,
    __half* __restrict__ wt2)
{
    int idx = blockIdx.x * blockDim.x + threadIdx.x;
    const float *Ws, *Wn;
    __half* wt;
    int NC, local;
    if (idx < 131072)      { Ws = Ws0; Wn = Wn0; wt = wt0; NC = 256; local = idx; }
    else if (idx < 262144) { Ws = Ws1; Wn = Wn1; wt = wt1; NC = 256; local = idx - 131072; }
    else if (idx < 294912) { Ws = Ws2; Wn = Wn2; wt = wt2; NC = 64;  local = idx - 262144; }
    else return;
    int n = local >> 9, k = local & 511;
    float v = (k < 256) ? Ws[(size_t)k * NC + n] : Wn[(size_t)(k - 256) * NC + n];
    wt[local] = __float2half_rn(v);
}

// ---------------------------------------------------------------------------
// Edge aggregation: 4 edges/warp, batched LDG.128 gather, vector REDs.
// RELU: apply fmaxf(x,0) to gathered values (deferred layer-1 activation).
// ---------------------------------------------------------------------------
template<bool RELU>
__global__ void sage_aggregate(const float* __restrict__ h,
                               const int*   __restrict__ src,
                               const int*   __restrict__ dst,
                               float*       __restrict__ agg,
                               float*       __restrict__ deg,
                               int E)
{
    int warp = (int)(blockIdx.x * (blockDim.x >> 5) + (threadIdx.x >> 5));
    int lane = threadIdx.x & 31;
    int e0 = warp * 4;
    if (e0 >= E) return;
    int n = E - e0;
    if (n > 4) n = 4;

    int s[4], d[4];
#pragma unroll
    for (int e = 0; e < 4; e++) {
        int idx = (e < n) ? e0 + e : e0;
        s[e] = __ldg(src + idx);
        d[e] = __ldg(dst + idx);
    }
    float4 v[4][2];
#pragma unroll
    for (int e = 0; e < 4; e++) {
        if (e < n) {
            const float4* hs = (const float4*)(h + (size_t)s[e] * DF) + lane;
            v[e][0] = __ldg(hs);
            v[e][1] = __ldg(hs + 32);
            if (RELU) {
#pragma unroll
                for (int q = 0; q < 2; q++) {
                    v[e][q].x = fmaxf(v[e][q].x, 0.f);
                    v[e][q].y = fmaxf(v[e][q].y, 0.f);
                    v[e][q].z = fmaxf(v[e][q].z, 0.f);
                    v[e][q].w = fmaxf(v[e][q].w, 0.f);
                }
            }
        }
    }
#pragma unroll
    for (int e = 0; e < 4; e++) {
        if (e < n) {
            float* p = agg + (size_t)d[e] * DF + lane * 4;
            asm volatile("red.global.add.v4.f32 [%0], {%1, %2, %3, %4};"
                         :: "l"(p), "f"(v[e][0].x), "f"(v[e][0].y),
                            "f"(v[e][0].z), "f"(v[e][0].w) : "memory");
            asm volatile("red.global.add.v4.f32 [%0], {%1, %2, %3, %4};"
                         :: "l"(p + 128), "f"(v[e][1].x), "f"(v[e][1].y),
                            "f"(v[e][1].z), "f"(v[e][1].w) : "memory");
        }
    }
#pragma unroll
    for (int e = 0; e < 4; e++)
        if (lane == e && e < n) atomicAdd(deg + d[e], 1.0f);
}

// ---------------------------------------------------------------------------
// GEMM tile: CTA 128xBN, BK=64, 8 warps (4Mx2N), warp 32x(BN/2).
//   NEIGH: red.global.add  invd[m]*(agg@Wn)[m,n]  into out (no output read)
//   !NEIGH: out = relu?(A)@Ws + bias   (RELUA applies fmaxf to A on load)
// A fp32 -> regs -> fp16 smem (pitch 144 = 128B data + 16B skew).
// B fp16 via cp.async, double-buffered; 4 barrier iterations.
// ---------------------------------------------------------------------------
template<int BN, bool NEIGH, bool RELUA>
__device__ __forceinline__ void gemm_tile(
    const float* __restrict__ A, const float* __restrict__ deg,
    const __half* __restrict__ wt, int koff,
    const float* __restrict__ bias, float* __restrict__ out,
    int M, int NCOLS, int bm0, int bn0, char* smem)
{
    constexpr int APITCH = 144;
    constexpr int ASTG   = 128 * APITCH;
    constexpr int BSTG   = BN * APITCH;
    constexpr int SS     = ASTG + BSTG;
    constexpr int NT8    = BN / 16;
    constexpr int NBSEG  = BN / 32;
    constexpr int WN     = BN / 2;

    float* s_invd = (float*)smem;
    char*  stg    = smem + 1024;
    uint32_t stg_u = smem_u32(stg);

    int tid  = threadIdx.x;
    int lane = tid & 31, wid = tid >> 5;
    int wm = wid & 3, wn = wid >> 2;

    if (NEIGH) {
        if (tid < 128) {
            int r = bm0 + tid;
            float dg = (r < M) ? deg[r] : 1.0f;
            s_invd[tid] = 1.0f / fmaxf(dg, 1.0f);
        }
        __syncthreads();
    }

    uint4 ah[4];

    auto prepA = [&](int kt) {
        int kc = kt * 64;
#pragma unroll
        for (int i = 0; i < 4; i++) {
            int seg = tid + 256 * i;
            int row = seg >> 3, c8 = (seg & 7) * 8;
            int gr = bm0 + row;
            float4 v0 = make_float4(0.f, 0.f, 0.f, 0.f), v1 = v0;
            if (gr < M) {
                const float4* p = (const float4*)(A + (size_t)gr * DF + kc + c8);
                v0 = __ldg(p); v1 = __ldg(p + 1);
                if (RELUA) {
                    v0.x = fmaxf(v0.x, 0.f); v0.y = fmaxf(v0.y, 0.f);
                    v0.z = fmaxf(v0.z, 0.f); v0.w = fmaxf(v0.w, 0.f);
                    v1.x = fmaxf(v1.x, 0.f); v1.y = fmaxf(v1.y, 0.f);
                    v1.z = fmaxf(v1.z, 0.f); v1.w = fmaxf(v1.w, 0.f);
                }
            }
            ah[i] = cvt8(v0, v1);
        }
    };

    auto storeA = [&](int s) {
        char* base = stg + s * SS;
#pragma unroll
        for (int i = 0; i < 4; i++) {
            int seg = tid + 256 * i;
            int row = seg >> 3, cc = (seg & 7) * 16;
            *(uint4*)(base + row * APITCH + cc) = ah[i];
        }
    };

    auto issueB = [&](int kt, int s) {
        int kg = kt * 64;
        uint32_t bbase = stg_u + s * SS + ASTG;
#pragma unroll
        for (int i = 0; i < NBSEG; i++) {
            int seg = tid + 256 * i;
            int row = seg >> 3, cc = (seg & 7) * 16;
            uint32_t sa = bbase + row * APITCH + cc;
            const __half* g = wt + (size_t)(bn0 + row) * 512 + koff + kg + (seg & 7) * 8;
            asm volatile("cp.async.cg.shared.global [%0], [%1], 16;"
                         :: "r"(sa), "l"(g));
        }
        asm volatile("cp.async.commit_group;" ::: "memory");
    };

    float acc[2][NT8][4] = {};

    issueB(0, 0);
    prepA(0);

#pragma unroll 1
    for (int kt = 0; kt < 4; kt++) {
        int s = kt & 1;
        storeA(s);
        asm volatile("cp.async.wait_group 0;" ::: "memory");
        __syncthreads();
        if (kt < 3) {
            issueB(kt + 1, 1 - s);
            prepA(kt + 1);
        }

        uint32_t abase = stg_u + s * SS;
        uint32_t bbase = abase + ASTG;
#pragma unroll
        for (int ks = 0; ks < 4; ks++) {
            uint32_t af[2][4], bf[NT8][2];
#pragma unroll
            for (int mt = 0; mt < 2; mt++) {
                int r  = wm * 32 + mt * 16 + (lane & 7) + ((lane >> 3) & 1) * 8;
                int kb = ks * 16 + ((lane >> 4) & 1) * 8;
                ldsm4(af[mt], abase + r * APITCH + kb * 2);
            }
#pragma unroll
            for (int p = 0; p < NT8 / 2; p++) {
                int n  = wn * WN + p * 16 + (lane & 7) + ((lane >> 4) & 1) * 8;
                int kb = ks * 16 + ((lane >> 3) & 1) * 8;
                uint32_t th[4];
                ldsm4(th, bbase + n * APITCH + kb * 2);
                bf[2 * p][0] = th[0]; bf[2 * p][1] = th[1];
                bf[2 * p + 1][0] = th[2]; bf[2 * p + 1][1] = th[3];
            }
#pragma unroll
            for (int mt = 0; mt < 2; mt++)
#pragma unroll
                for (int nt = 0; nt < NT8; nt++)
                    mma16816(acc[mt][nt], af[mt], bf[nt]);
        }
    }

    // ---- epilogue ----
#pragma unroll
    for (int mt = 0; mt < 2; mt++) {
        int rr = wm * 32 + mt * 16 + (lane >> 2);
        int r0 = bm0 + rr;
        float sc0 = NEIGH ? s_invd[rr]     : 0.f;
        float sc1 = NEIGH ? s_invd[rr + 8] : 0.f;
#pragma unroll
        for (int nt = 0; nt < NT8; nt++) {
            int col = bn0 + wn * WN + nt * 8 + (lane & 3) * 2;
            if (NEIGH) {
                float o0x = acc[mt][nt][0] * sc0, o0y = acc[mt][nt][1] * sc0;
                float o1x = acc[mt][nt][2] * sc1, o1y = acc[mt][nt][3] * sc1;
                if (r0 < M) {
                    float* p = out + (size_t)r0 * NCOLS + col;
                    asm volatile("red.global.add.v2.f32 [%0], {%1, %2};"
                                 :: "l"(p), "f"(o0x), "f"(o0y) : "memory");
                }
                if (r0 + 8 < M) {
                    float* p = out + (size_t)(r0 + 8) * NCOLS + col;
                    asm volatile("red.global.add.v2.f32 [%0], {%1, %2};"
                                 :: "l"(p), "f"(o1x), "f"(o1y) : "memory");
                }
            } else {
                float2 bv = *(const float2*)(bias + col);
                float2 o0, o1;
                o0.x = acc[mt][nt][0] + bv.x; o0.y = acc[mt][nt][1] + bv.y;
                o1.x = acc[mt][nt][2] + bv.x; o1.y = acc[mt][nt][3] + bv.y;
                if (r0 < M)
                    *(float2*)(out + (size_t)r0 * NCOLS + col) = o0;
                if (r0 + 8 < M)
                    *(float2*)(out + (size_t)(r0 + 8) * NCOLS + col) = o1;
            }
        }
    }
}

template<int BN, bool RELUA>
__global__ __launch_bounds__(256)
void sage_gemm_self(const float* __restrict__ h,
                    const __half* __restrict__ wt,
                    const float* __restrict__ bias,
                    float* __restrict__ out, int M, int NCOLS)
{
    extern __shared__ char smem[];
    gemm_tile<BN, false, RELUA>(h, nullptr, wt, 0, bias, out, M, NCOLS,
                                blockIdx.y * 128, blockIdx.x * BN, smem);
}

template<int BN>
__global__ __launch_bounds__(256)
void sage_gemm_neigh(const float* __restrict__ agg,
                     const float* __restrict__ deg,
                     const __half* __restrict__ wt,
                     float* __restrict__ out, int M, int NCOLS)
{
    extern __shared__ char smem[];
    gemm_tile<BN, true, false>(agg, deg, wt, 256, nullptr, out, M, NCOLS,
                               blockIdx.y * 128, blockIdx.x * BN, smem);
}

// ---------------------------------------------------------------------------
// Launch
// ---------------------------------------------------------------------------
extern "C" void kernel_launch(void* const* d_in, const int* in_sizes, int n_in,
                              void* d_out, int out_size)
{
    const float* x    = (const float*)d_in[0];
    const int*   src0 = (const int*)d_in[1];
    const int*   dst0 = (const int*)d_in[2];
    const int*   src1 = (const int*)d_in[3];
    const int*   dst1 = (const int*)d_in[4];
    const int*   src2 = (const int*)d_in[5];
    const int*   dst2 = (const int*)d_in[6];

    int wb = n_in - 9;
    const float* Ws0 = (const float*)d_in[wb + 0];
    const float* Wn0 = (const float*)d_in[wb + 1];
    const float* b0  = (const float*)d_in[wb + 2];
    const float* Ws1 = (const float*)d_in[wb + 3];
    const float* Wn1 = (const float*)d_in[wb + 4];
    const float* b1  = (const float*)d_in[wb + 5];
    const float* Ws2 = (const float*)d_in[wb + 6];
    const float* Wn2 = (const float*)d_in[wb + 7];
    const float* b2  = (const float*)d_in[wb + 8];

    int E0 = in_sizes[1];
    int E1 = in_sizes[3];
    int E2 = in_sizes[5];

    float *scr, *h1, *h2;
    int *bcur, *ssrc, *sdst;
    __half *wt0, *wt1, *wt2;
    cudaGetSymbolAddress((void**)&scr,  g_scr);
    cudaGetSymbolAddress((void**)&h1,   g_h1);
    cudaGetSymbolAddress((void**)&h2,   g_h2);
    cudaGetSymbolAddress((void**)&bcur, g_bcur);
    cudaGetSymbolAddress((void**)&ssrc, g_ssrc);
    cudaGetSymbolAddress((void**)&sdst, g_sdst);
    cudaGetSymbolAddress((void**)&wt0,  g_wt0);
    cudaGetSymbolAddress((void**)&wt1,  g_wt1);
    cudaGetSymbolAddress((void**)&wt2,  g_wt2);

    int*   hist = (int*)(scr + HIST_OFF);
    float* agg0 = scr + AGG0_OFF;
    float* deg0 = scr + DEG0_OFF;
    float* agg1 = scr + AGG1_OFF;
    float* deg1 = scr + DEG1_OFF;
    float* agg2 = scr + AGG2_OFF;
    float* deg2 = scr + DEG2_OFF;

    const int SMEM128 = 1024 + 2 * (18432 + 128 * 144);  // 74752
    const int SMEM64  = 1024 + 2 * (18432 + 64 * 144);   // 56320
    cudaFuncSetAttribute(sage_gemm_self<128, false>,
                         cudaFuncAttributeMaxDynamicSharedMemorySize, SMEM128);
    cudaFuncSetAttribute(sage_gemm_self<64, true>,
                         cudaFuncAttributeMaxDynamicSharedMemorySize, SMEM64);
    cudaFuncSetAttribute(sage_gemm_neigh<128>,
                         cudaFuncAttributeMaxDynamicSharedMemorySize, SMEM128);
    cudaFuncSetAttribute(sage_gemm_neigh<64>,
                         cudaFuncAttributeMaxDynamicSharedMemorySize, SMEM64);

    cudaStream_t s2;
    cudaStreamCreateWithFlags(&s2, cudaStreamNonBlocking);
    cudaEvent_t evStart, evZ, evJ0, evJ1, evJ2, evN0, evN1;
    cudaEventCreateWithFlags(&evStart, cudaEventDisableTiming);
    cudaEventCreateWithFlags(&evZ,     cudaEventDisableTiming);
    cudaEventCreateWithFlags(&evJ0,    cudaEventDisableTiming);
    cudaEventCreateWithFlags(&evJ1,    cudaEventDisableTiming);
    cudaEventCreateWithFlags(&evJ2,    cudaEventDisableTiming);
    cudaEventCreateWithFlags(&evN0,    cudaEventDisableTiming);
    cudaEventCreateWithFlags(&evN1,    cudaEventDisableTiming);

    // fork: default owns partition chain + agg + neigh; s2 owns the big
    // scratch memset (off the critical path), weight convert, self-GEMMs.
    cudaEventRecord(evStart, 0);
    cudaStreamWaitEvent(s2, evStart, 0);

    // default: tiny hist memset only, then partition chain
    cudaMemsetAsync(scr, 0, sizeof(float) * NBUK);
    edge_hist<<<(E0 + 2047) / 2048, 256>>>(src0, E0, hist);
    bucket_scan<<<1, NBUK>>>(hist, bcur);
    edge_partition<<<(E0 + 2047) / 2048, 256>>>(src0, dst0, E0, bcur, ssrc, sdst);

    // s2: big scratch memset (agg/deg for all layers) + weights + self0
    cudaMemsetAsync(scr + AGG0_OFF, 0,
                    sizeof(float) * (size_t)(SCR_TOT - AGG0_OFF), s2);
    cudaEventRecord(evZ, s2);
    convert_weights_all<<<(294912 + 255) / 256, 256, 0, s2>>>(
        Ws0, Wn0, Ws1, Wn1, Ws2, Wn2, wt0, wt1, wt2);
    sage_gemm_self<128, false><<<dim3(2, (N1C + 127) / 128), 256, SMEM128, s2>>>(
        x, wt0, b0, h1, N1C, 256);
    cudaEventRecord(evJ0, s2);

    // ---- Layer 0 (partitioned edges; wait for agg0/deg0 zeros) ----
    cudaStreamWaitEvent(0, evZ, 0);
    sage_aggregate<false><<<(E0 + 31) / 32, 256>>>(x, ssrc, sdst, agg0, deg0, E0);
    cudaStreamWaitEvent(0, evJ0, 0);
    sage_gemm_neigh<128><<<dim3(2, (N1C + 127) / 128), 256, SMEM128>>>(
        agg0, deg0, wt0, h1, N1C, 256);
    cudaEventRecord(evN0, 0);

    // s2: self1 after h1 complete
    cudaStreamWaitEvent(s2, evN0, 0);
    sage_gemm_self<128, false><<<dim3(2, (N2C + 127) / 128), 256, SMEM128, s2>>>(
        h1, wt1, b1, h2, N2C, 256);
    cudaEventRecord(evJ1, s2);

    // ---- Layer 1 (h2 stored pre-relu; consumers apply relu) ----
    sage_aggregate<false><<<(E1 + 31) / 32, 256>>>(h1, src1, dst1, agg1, deg1, E1);
    cudaStreamWaitEvent(0, evJ1, 0);
    sage_gemm_neigh<128><<<dim3(2, (N2C + 127) / 128), 256, SMEM128>>>(
        agg1, deg1, wt1, h2, N2C, 256);
    cudaEventRecord(evN1, 0);

    // s2: self2 after h2 complete (relu applied on A load)
    cudaStreamWaitEvent(s2, evN1, 0);
    sage_gemm_self<64, true><<<dim3(1, (N3C + 127) / 128), 256, SMEM64, s2>>>(
        h2, wt2, b2, (float*)d_out, N3C, 64);
    cudaEventRecord(evJ2, s2);

    // ---- Layer 2 (relu applied on gather) ----
    sage_aggregate<true><<<(E2 + 31) / 32, 256>>>(h2, src2, dst2, agg2, deg2, E2);
    cudaStreamWaitEvent(0, evJ2, 0);   // self2 wrote d_out base; RED adds after
    sage_gemm_neigh<64><<<dim3(1, (N3C + 127) / 128), 256, SMEM64>>>(
        agg2, deg2, wt2, (float*)d_out, N3C, 64);
}